// round 1
// baseline (speedup 1.0000x reference)
#include <cuda_runtime.h>
#include <math.h>

#define NB      296          // blocks (2 per SM, one wave on 148 SMs)
#define NTHR    256          // threads per block
#define NGROUPS (NB * (NTHR / 8))

// Folded score weights: score_h = u_h . hidden + c_h   (scale 1/sqrt(16) folded in)
__device__ float g_u[4][64];
__device__ float g_c[4];
// Per-block softmax partials: [block][head][ m, s, acc[64] ]
__device__ float g_part[NB][4][66];

__device__ __forceinline__ float silu_f(float x) {
    // x * sigmoid(x) = x / (1 + e^-x); __expf + approx-div -> 2 MUFU, ~1e-6 rel err
    return __fdividef(x, 1.0f + __expf(-x));
}

// ---------------------------------------------------------------------------
// Prep: fold q, Wk, W2 into u_h (R^64) and c_h per head.  1 block, 64 threads.
// ---------------------------------------------------------------------------
__global__ void prep_kernel(const float* __restrict__ W2,
                            const float* __restrict__ b2,
                            const float* __restrict__ query,
                            const float* __restrict__ ipw,   // in_proj_w (192,64)
                            const float* __restrict__ ipb)   // in_proj_b (192)
{
    __shared__ float qv[64];
    __shared__ float tt[4][64];
    const int j = threadIdx.x;

    // q[j] = query . Wq[j] + bq[j]   (Wq = rows 0..63)
    float a = ipb[j];
    #pragma unroll 4
    for (int m = 0; m < 64; m++) a = fmaf(query[m], ipw[j * 64 + m], a);
    qv[j] = a;
    __syncthreads();

    // t_h[j] = sum_d q[16h+d] * Wk[16h+d][j]   (Wk = rows 64..127)
    #pragma unroll
    for (int h = 0; h < 4; h++) {
        float t = 0.f;
        #pragma unroll 4
        for (int d = 0; d < 16; d++)
            t = fmaf(qv[h * 16 + d], ipw[(64 + h * 16 + d) * 64 + j], t);
        tt[h][j] = t;
    }
    __syncthreads();

    // u_h[j] = sum_jj t_h[jj] * W2[jj][j], scaled by 0.25 (1/sqrt(hd))
    #pragma unroll
    for (int h = 0; h < 4; h++) {
        float u = 0.f;
        #pragma unroll 4
        for (int jj = 0; jj < 64; jj++)
            u = fmaf(tt[h][jj], W2[jj * 64 + j], u);
        g_u[h][j] = 0.25f * u;
    }
    // c_h = q_h . bk_h + t_h . b2, scaled
    if (j < 4) {
        float c = 0.f;
        for (int d = 0; d < 16; d++) c = fmaf(qv[j * 16 + d], ipb[64 + j * 16 + d], c);
        for (int jj = 0; jj < 64; jj++) c = fmaf(tt[j][jj], b2[jj], c);
        g_c[j] = 0.25f * c;
    }
}

// ---------------------------------------------------------------------------
// Main: per point compute hidden (silu MLP layer 1), scores via folded u, and
// online-softmax accumulate sum_n attn_hn * hidden_n.  8 lanes per point.
// ---------------------------------------------------------------------------
__global__ void __launch_bounds__(NTHR, 2)
main_kernel(const float* __restrict__ rr,
            const float* __restrict__ ri,
            const float* __restrict__ W1,
            const float* __restrict__ b1,
            int N)
{
    const int tid  = threadIdx.x;
    const int lane = tid & 31;
    const int sub  = tid & 7;                      // j-chunk: [sub*8, sub*8+8)
    const int gid  = (blockIdx.x * NTHR + tid) >> 3;   // group id (one point at a time)
    const unsigned gmask = 0xFFu << (lane & 24);   // the 8 lanes of this group

    // Per-lane constants
    float w1a[8], w1b[8], b1v[8], u4[4][8];
    #pragma unroll
    for (int jj = 0; jj < 8; jj++) {
        const int j = sub * 8 + jj;
        w1a[jj] = W1[2 * j];
        w1b[jj] = W1[2 * j + 1];
        b1v[jj] = b1[j];
        #pragma unroll
        for (int h = 0; h < 4; h++) u4[h][jj] = g_u[h][j];
    }
    float c4[4];
    #pragma unroll
    for (int h = 0; h < 4; h++) c4[h] = g_c[h];

    // Online-softmax state (replicated across the 8 lanes of a group; acc is
    // distributed: this lane holds acc[h][j in chunk])
    float m4[4], s4[4], acc[4][8];
    #pragma unroll
    for (int h = 0; h < 4; h++) {
        m4[h] = -1e30f; s4[h] = 0.f;
        #pragma unroll
        for (int jj = 0; jj < 8; jj++) acc[h][jj] = 0.f;
    }

    for (int p = gid; p < N; p += NGROUPS) {
        const float r  = __ldg(rr + p);
        const float im = __ldg(ri + p);

        float hid[8];
        float part[4] = {0.f, 0.f, 0.f, 0.f};
        #pragma unroll
        for (int jj = 0; jj < 8; jj++) {
            const float x  = fmaf(im, w1b[jj], fmaf(r, w1a[jj], b1v[jj]));
            const float hv = silu_f(x);
            hid[jj] = hv;
            #pragma unroll
            for (int h = 0; h < 4; h++) part[h] = fmaf(u4[h][jj], hv, part[h]);
        }
        // Butterfly reduce over the 8 group lanes (group-scoped mask: trip
        // counts can differ by 1 between groups in the same warp)
        #pragma unroll
        for (int off = 1; off < 8; off <<= 1) {
            #pragma unroll
            for (int h = 0; h < 4; h++)
                part[h] += __shfl_xor_sync(gmask, part[h], off);
        }

        #pragma unroll
        for (int h = 0; h < 4; h++) {
            const float sc = part[h] + c4[h];
            float w;
            if (sc > m4[h]) {                       // rare after warmup (~log n)
                const float corr = __expf(m4[h] - sc);
                m4[h] = sc;
                s4[h] = fmaf(s4[h], corr, 1.0f);
                #pragma unroll
                for (int jj = 0; jj < 8; jj++) acc[h][jj] *= corr;
                w = 1.0f;
            } else {
                w = __expf(sc - m4[h]);
                s4[h] += w;
            }
            #pragma unroll
            for (int jj = 0; jj < 8; jj++) acc[h][jj] = fmaf(w, hid[jj], acc[h][jj]);
        }
    }

    // Combine the 4 groups of this warp (xor 8, xor 16); full warp reconverged.
    #pragma unroll
    for (int off = 8; off <= 16; off <<= 1) {
        #pragma unroll
        for (int h = 0; h < 4; h++) {
            const float om = __shfl_xor_sync(0xffffffffu, m4[h], off);
            const float os = __shfl_xor_sync(0xffffffffu, s4[h], off);
            const float nm = fmaxf(m4[h], om);
            const float c1 = __expf(m4[h] - nm);
            const float c2 = __expf(om - nm);
            s4[h] = s4[h] * c1 + os * c2;
            #pragma unroll
            for (int jj = 0; jj < 8; jj++) {
                const float oa = __shfl_xor_sync(0xffffffffu, acc[h][jj], off);
                acc[h][jj] = acc[h][jj] * c1 + oa * c2;
            }
            m4[h] = nm;
        }
    }

    // Block combine via shared memory (8 warps)
    __shared__ float sh_m[8][4];
    __shared__ float sh_s[8][4];
    __shared__ float sh_acc[8][4][64];
    const int wid = tid >> 5;
    if (lane < 8) {
        #pragma unroll
        for (int h = 0; h < 4; h++) {
            #pragma unroll
            for (int jj = 0; jj < 8; jj++)
                sh_acc[wid][h][lane * 8 + jj] = acc[h][jj];
            if (lane == 0) { sh_m[wid][h] = m4[h]; sh_s[wid][h] = s4[h]; }
        }
    }
    __syncthreads();

    // 256 threads = 4 heads x 64 dims: fold the 8 warp-partials, write g_part
    {
        const int h = tid >> 6;
        const int j = tid & 63;
        float M = -1e30f;
        #pragma unroll
        for (int w = 0; w < 8; w++) M = fmaxf(M, sh_m[w][h]);
        float A = 0.f, S = 0.f;
        #pragma unroll
        for (int w = 0; w < 8; w++) {
            const float e = __expf(sh_m[w][h] - M);
            A = fmaf(e, sh_acc[w][h][j], A);
            S = fmaf(e, sh_s[w][h], S);
        }
        g_part[blockIdx.x][h][2 + j] = A;
        if (j == 0) { g_part[blockIdx.x][h][0] = M; g_part[blockIdx.x][h][1] = S; }
    }
}

// ---------------------------------------------------------------------------
// Final: combine per-block partials, apply W2/b2, Wv/bv, out_proj.  1 block.
// ---------------------------------------------------------------------------
__global__ void final_kernel(const float* __restrict__ W2,
                             const float* __restrict__ b2,
                             const float* __restrict__ ipw,
                             const float* __restrict__ ipb,
                             const float* __restrict__ opw,
                             const float* __restrict__ opb,
                             float* __restrict__ out)
{
    __shared__ float sh_p[4][64];
    __shared__ float sh_hbar[4][64];
    __shared__ float sh_pooled[64];
    const int t = threadIdx.x;
    const int h = t >> 6;
    const int j = t & 63;

    float M = -1e30f;
    for (int b = 0; b < NB; b++) M = fmaxf(M, g_part[b][h][0]);
    float A = 0.f, S = 0.f;
    for (int b = 0; b < NB; b++) {
        const float e = __expf(g_part[b][h][0] - M);
        A = fmaf(e, g_part[b][h][2 + j], A);
        S = fmaf(e, g_part[b][h][1], S);
    }
    sh_p[h][j] = A / S;     // E[hidden] under attn, head h
    __syncthreads();

    // hbar_h[j] = W2[j] . p_h + b2[j]
    float hb = b2[j];
    #pragma unroll 4
    for (int m = 0; m < 64; m++) hb = fmaf(W2[j * 64 + m], sh_p[h][m], hb);
    sh_hbar[h][j] = hb;
    __syncthreads();

    // pooled[16h+d] = Wv[16h+d] . hbar_h + bv[16h+d]   (Wv = rows 128..191)
    if (t < 64) {
        const int e = t, hh = t >> 4;
        float pl = ipb[128 + e];
        #pragma unroll 4
        for (int jj = 0; jj < 64; jj++)
            pl = fmaf(ipw[(128 + e) * 64 + jj], sh_hbar[hh][jj], pl);
        sh_pooled[e] = pl;
    }
    __syncthreads();

    if (t < 64) {
        float o = opb[t];
        #pragma unroll 4
        for (int e = 0; e < 64; e++) o = fmaf(opw[t * 64 + e], sh_pooled[e], o);
        out[t] = o;
    }
}

// ---------------------------------------------------------------------------
extern "C" void kernel_launch(void* const* d_in, const int* in_sizes, int n_in,
                              void* d_out, int out_size)
{
    const float* rr    = (const float*)d_in[0];   // rho_real (1024*1024)
    const float* ri    = (const float*)d_in[1];   // rho_imag
    // d_in[2..5]: l_A, l_B, Z_A, Z_B — unused by the reference math
    const float* W1    = (const float*)d_in[6];   // (64,2)
    const float* b1    = (const float*)d_in[7];   // (64)
    const float* W2    = (const float*)d_in[8];   // (64,64)
    const float* b2    = (const float*)d_in[9];   // (64)
    const float* query = (const float*)d_in[10];  // (1,64)
    const float* ipw   = (const float*)d_in[11];  // (192,64)
    const float* ipb   = (const float*)d_in[12];  // (192)
    const float* opw   = (const float*)d_in[13];  // (64,64)
    const float* opb   = (const float*)d_in[14];  // (64)
    const int N = in_sizes[0];

    prep_kernel<<<1, 64>>>(W2, b2, query, ipw, ipb);
    main_kernel<<<NB, NTHR>>>(rr, ri, W1, b1, N);
    final_kernel<<<1, 256>>>(W2, b2, ipw, ipb, opw, opb, (float*)d_out);
}

// round 2
// speedup vs baseline: 1.1302x; 1.1302x over previous
#include <cuda_runtime.h>
#include <math.h>

#define NB      148              // one block per SM, single wave
#define NTHR    384              // 12 warps, ~170 regs/thread available
#define GPB     (NTHR / 8)       // 48 groups per block
#define NGROUPS (NB * GPB)       // 7104
#define NWARP   (NTHR / 32)      // 12

typedef unsigned long long ull;

// Per-block softmax partials: [block][head][ m, s, acc[64] ]
__device__ float g_part[NB][4][66];

// ---- packed f32x2 helpers (ptxas never auto-fuses FFMA2) --------------------
__device__ __forceinline__ ull pk2(float lo, float hi) {
    ull r; asm("mov.b64 %0,{%1,%2};" : "=l"(r) : "f"(lo), "f"(hi)); return r;
}
__device__ __forceinline__ void upk2(float& lo, float& hi, ull p) {
    asm("mov.b64 {%0,%1},%2;" : "=f"(lo), "=f"(hi) : "l"(p));
}
__device__ __forceinline__ ull fma2(ull a, ull b, ull c) {
    ull d; asm("fma.rn.f32x2 %0,%1,%2,%3;" : "=l"(d) : "l"(a), "l"(b), "l"(c)); return d;
}
__device__ __forceinline__ ull mul2(ull a, ull b) {
    ull d; asm("mul.rn.f32x2 %0,%1,%2;" : "=l"(d) : "l"(a), "l"(b)); return d;
}
__device__ __forceinline__ ull add2(ull a, ull b) {
    ull d; asm("add.rn.f32x2 %0,%1,%2;" : "=l"(d) : "l"(a), "l"(b)); return d;
}
__device__ __forceinline__ float tanh_ap(float x) {
    float y; asm("tanh.approx.f32 %0,%1;" : "=f"(y) : "f"(x)); return y;
}
// silu(x) = x*sigmoid(x) = h + h*tanh(h), h = x/2  -> 1 MUFU instead of 2
__device__ __forceinline__ ull silu2(ull xpk, ull halfpk) {
    ull hpk = mul2(xpk, halfpk);
    float h0, h1; upk2(h0, h1, hpk);
    ull tpk = pk2(tanh_ap(h0), tanh_ap(h1));
    return fma2(hpk, tpk, hpk);
}

// -----------------------------------------------------------------------------
// Fused kernel: per-block inline prep (fold q,Wk,W2 -> u,c) + streaming
// online-softmax over points.  8 lanes per point, f32x2-packed math.
// -----------------------------------------------------------------------------
__global__ void __launch_bounds__(NTHR, 1)
main_kernel(const float* __restrict__ rr,
            const float* __restrict__ ri,
            const float* __restrict__ W1,
            const float* __restrict__ b1,
            const float* __restrict__ W2,
            const float* __restrict__ b2,
            const float* __restrict__ query,
            const float* __restrict__ ipw,   // in_proj_w (192,64)
            const float* __restrict__ ipb,   // in_proj_b (192)
            int N)
{
    __shared__ float qv[64];
    __shared__ float tt[4][64];
    __shared__ float sh_u[4][64];
    __shared__ float sh_c[4];
    __shared__ float sh_m[NWARP][4];
    __shared__ float sh_s[NWARP][4];
    __shared__ float sh_acc[NWARP][4][64];

    const int tid  = threadIdx.x;
    const int lane = tid & 31;
    const int sub  = tid & 7;
    const unsigned gmask = 0xFFu << (lane & 24);

    // ---- inline prep (every block redundantly; ~25K FMA, L2-resident) ------
    if (tid < 64) {
        float a = ipb[tid], a2 = 0.f;
        #pragma unroll 8
        for (int m = 0; m < 64; m += 2) {
            a  = fmaf(query[m],     ipw[tid * 64 + m],     a);
            a2 = fmaf(query[m + 1], ipw[tid * 64 + m + 1], a2);
        }
        qv[tid] = a + a2;
    }
    __syncthreads();
    if (tid < 256) {
        const int h = tid >> 6, j = tid & 63;
        float t = 0.f;
        #pragma unroll 8
        for (int d = 0; d < 16; d++)
            t = fmaf(qv[h * 16 + d], ipw[(64 + h * 16 + d) * 64 + j], t);
        tt[h][j] = t;
    }
    __syncthreads();
    if (tid < 256) {
        const int h = tid >> 6, j = tid & 63;
        float u = 0.f, u2 = 0.f;
        #pragma unroll 8
        for (int jj = 0; jj < 64; jj += 2) {
            u  = fmaf(tt[h][jj],     W2[jj * 64 + j],       u);
            u2 = fmaf(tt[h][jj + 1], W2[(jj + 1) * 64 + j], u2);
        }
        sh_u[h][j] = 0.25f * (u + u2);       // fold 1/sqrt(hd)=0.25
    } else if (tid < 260) {
        const int h = tid - 256;
        float c = 0.f;
        for (int d = 0; d < 16; d++) c = fmaf(qv[h * 16 + d], ipb[64 + h * 16 + d], c);
        for (int jj = 0; jj < 64; jj++) c = fmaf(tt[h][jj], b2[jj], c);
        sh_c[h] = 0.25f * c;
    }
    __syncthreads();

    // ---- per-lane packed constants -----------------------------------------
    const int j0 = sub * 8;
    ull w1ap[4], w1bp[4], b1p[4], u4p[4][4];
    #pragma unroll
    for (int k = 0; k < 4; k++) {
        const int j = j0 + 2 * k;
        w1ap[k] = pk2(W1[2 * j],     W1[2 * j + 2]);
        w1bp[k] = pk2(W1[2 * j + 1], W1[2 * j + 3]);
        b1p[k]  = pk2(b1[j], b1[j + 1]);
        #pragma unroll
        for (int h = 0; h < 4; h++) u4p[h][k] = pk2(sh_u[h][j], sh_u[h][j + 1]);
    }
    float c4[4];
    #pragma unroll
    for (int h = 0; h < 4; h++) c4[h] = sh_c[h];
    const ull halfpk = pk2(0.5f, 0.5f);

    // ---- online softmax state ----------------------------------------------
    float m4[4], s4[4];
    ull accp[4][4];
    #pragma unroll
    for (int h = 0; h < 4; h++) {
        m4[h] = -1e30f; s4[h] = 0.f;
        #pragma unroll
        for (int k = 0; k < 4; k++) accp[h][k] = 0ull;
    }

    const int gid = blockIdx.x * GPB + (tid >> 3);
    for (int p = gid; p < N; p += NGROUPS) {
        const float r  = __ldg(rr + p);
        const float im = __ldg(ri + p);
        const ull rpk = pk2(r, r);
        const ull ipk = pk2(im, im);

        ull hidp[4];
        ull partp[4] = {0ull, 0ull, 0ull, 0ull};
        #pragma unroll
        for (int k = 0; k < 4; k++) {
            ull x = fma2(rpk, w1ap[k], b1p[k]);
            x = fma2(ipk, w1bp[k], x);
            hidp[k] = silu2(x, halfpk);
            #pragma unroll
            for (int h = 0; h < 4; h++)
                partp[h] = fma2(u4p[h][k], hidp[k], partp[h]);
        }
        float sc4[4];
        #pragma unroll
        for (int h = 0; h < 4; h++) { float a, b; upk2(a, b, partp[h]); sc4[h] = a + b; }

        // butterfly over the 8 group lanes (group-scoped mask: trip counts
        // differ by 1 across groups in the same warp)
        #pragma unroll
        for (int off = 1; off < 8; off <<= 1) {
            #pragma unroll
            for (int h = 0; h < 4; h++)
                sc4[h] += __shfl_xor_sync(gmask, sc4[h], off);
        }

        #pragma unroll
        for (int h = 0; h < 4; h++) {
            const float sc = sc4[h] + c4[h];
            float w;
            if (sc > m4[h]) {                      // group-uniform, rare (~log n)
                const float corr = __expf(m4[h] - sc);
                m4[h] = sc;
                s4[h] = fmaf(s4[h], corr, 1.0f);
                const ull cpk = pk2(corr, corr);
                #pragma unroll
                for (int k = 0; k < 4; k++) accp[h][k] = mul2(accp[h][k], cpk);
                w = 1.0f;
            } else {
                w = __expf(sc - m4[h]);
                s4[h] += w;
            }
            const ull wpk = pk2(w, w);
            #pragma unroll
            for (int k = 0; k < 4; k++)
                accp[h][k] = fma2(wpk, hidp[k], accp[h][k]);
        }
    }

    // ---- combine 4 groups of this warp (xor 8, 16); warp reconverged -------
    #pragma unroll
    for (int off = 8; off <= 16; off <<= 1) {
        #pragma unroll
        for (int h = 0; h < 4; h++) {
            const float om = __shfl_xor_sync(0xffffffffu, m4[h], off);
            const float os = __shfl_xor_sync(0xffffffffu, s4[h], off);
            const float nm = fmaxf(m4[h], om);
            const float c1 = __expf(m4[h] - nm);
            const float c2 = __expf(om - nm);
            s4[h] = s4[h] * c1 + os * c2;
            const ull c1p = pk2(c1, c1), c2p = pk2(c2, c2);
            #pragma unroll
            for (int k = 0; k < 4; k++) {
                const ull oa = __shfl_xor_sync(0xffffffffu, accp[h][k], off);
                accp[h][k] = add2(mul2(accp[h][k], c1p), mul2(oa, c2p));
            }
            m4[h] = nm;
        }
    }

    // ---- block combine via shared (12 warps) --------------------------------
    const int wid = tid >> 5;
    if (lane < 8) {
        #pragma unroll
        for (int h = 0; h < 4; h++) {
            #pragma unroll
            for (int k = 0; k < 4; k++) {
                float a, b; upk2(a, b, accp[h][k]);
                sh_acc[wid][h][lane * 8 + 2 * k]     = a;
                sh_acc[wid][h][lane * 8 + 2 * k + 1] = b;
            }
            if (lane == 0) { sh_m[wid][h] = m4[h]; sh_s[wid][h] = s4[h]; }
        }
    }
    __syncthreads();

    if (tid < 256) {
        const int h = tid >> 6;
        const int j = tid & 63;
        float M = -1e30f;
        #pragma unroll
        for (int w = 0; w < NWARP; w++) M = fmaxf(M, sh_m[w][h]);
        float A = 0.f, S = 0.f;
        #pragma unroll
        for (int w = 0; w < NWARP; w++) {
            const float e = __expf(sh_m[w][h] - M);
            A = fmaf(e, sh_acc[w][h][j], A);
            S = fmaf(e, sh_s[w][h], S);
        }
        g_part[blockIdx.x][h][2 + j] = A;
        if (j == 0) { g_part[blockIdx.x][h][0] = M; g_part[blockIdx.x][h][1] = S; }
    }
}

// -----------------------------------------------------------------------------
// Final: combine per-block partials, apply W2/b2, Wv/bv, out_proj.  1 block.
// -----------------------------------------------------------------------------
__global__ void final_kernel(const float* __restrict__ W2,
                             const float* __restrict__ b2,
                             const float* __restrict__ ipw,
                             const float* __restrict__ ipb,
                             const float* __restrict__ opw,
                             const float* __restrict__ opb,
                             float* __restrict__ out)
{
    __shared__ float sh_p[4][64];
    __shared__ float sh_hbar[4][64];
    __shared__ float sh_pooled[64];
    const int t = threadIdx.x;
    const int h = t >> 6;
    const int j = t & 63;

    float M = -1e30f;
    #pragma unroll 4
    for (int b = 0; b < NB; b++) M = fmaxf(M, g_part[b][h][0]);
    float A = 0.f, S = 0.f;
    #pragma unroll 4
    for (int b = 0; b < NB; b++) {
        const float e = __expf(g_part[b][h][0] - M);
        A = fmaf(e, g_part[b][h][2 + j], A);
        S = fmaf(e, g_part[b][h][1], S);
    }
    sh_p[h][j] = A / S;     // E[hidden] under attn, head h
    __syncthreads();

    float hb = b2[j];
    #pragma unroll 8
    for (int m = 0; m < 64; m++) hb = fmaf(W2[j * 64 + m], sh_p[h][m], hb);
    sh_hbar[h][j] = hb;
    __syncthreads();

    if (t < 64) {
        const int e = t, hh = t >> 4;
        float pl = ipb[128 + e];
        #pragma unroll 8
        for (int jj = 0; jj < 64; jj++)
            pl = fmaf(ipw[(128 + e) * 64 + jj], sh_hbar[hh][jj], pl);
        sh_pooled[e] = pl;
    }
    __syncthreads();

    if (t < 64) {
        float o = opb[t];
        #pragma unroll 8
        for (int e = 0; e < 64; e++) o = fmaf(opw[t * 64 + e], sh_pooled[e], o);
        out[t] = o;
    }
}

// -----------------------------------------------------------------------------
extern "C" void kernel_launch(void* const* d_in, const int* in_sizes, int n_in,
                              void* d_out, int out_size)
{
    const float* rr    = (const float*)d_in[0];   // rho_real (1024*1024)
    const float* ri    = (const float*)d_in[1];   // rho_imag
    // d_in[2..5]: l_A, l_B, Z_A, Z_B — unused by the reference math
    const float* W1    = (const float*)d_in[6];   // (64,2)
    const float* b1    = (const float*)d_in[7];   // (64)
    const float* W2    = (const float*)d_in[8];   // (64,64)
    const float* b2    = (const float*)d_in[9];   // (64)
    const float* query = (const float*)d_in[10];  // (1,64)
    const float* ipw   = (const float*)d_in[11];  // (192,64)
    const float* ipb   = (const float*)d_in[12];  // (192)
    const float* opw   = (const float*)d_in[13];  // (64,64)
    const float* opb   = (const float*)d_in[14];  // (64)
    const int N = in_sizes[0];

    main_kernel<<<NB, NTHR>>>(rr, ri, W1, b1, W2, b2, query, ipw, ipb, N);
    final_kernel<<<1, 256>>>(W2, b2, ipw, ipb, opw, opb, (float*)d_out);
}